// round 9
// baseline (speedup 1.0000x reference)
#include <cuda_runtime.h>
#include <cuda_bf16.h>
#include <cstdint>

#define B_MAX 16384

// ---------------- persistent scratch (__device__ globals; no allocations) ----
__device__ float g_w2T[1024 * 64];    // snn_w2 transposed: [h][o] = w2[o][h]
__device__ float g_nnw2T[1024 * 64];  // nn_w2 transposed: [h][o]
__device__ float g_fcT[1600 * 256];   // cnn_fc_w transposed: [k][o]
__device__ float g_combT[384 * 64];   // comb_w transposed: [c][o]
__device__ float g_snn[B_MAX * 64];
__device__ float g_nn[B_MAX * 64];
__device__ float g_cnn[B_MAX * 256];

// ---------------- weight transpose ------------------------------------------
__global__ void prep_kernel(const float* __restrict__ snn_w2,
                            const float* __restrict__ nn_w2,
                            const float* __restrict__ fc_w,
                            const float* __restrict__ comb_w) {
    int i = blockIdx.x * blockDim.x + threadIdx.x;
    if (i < 1024 * 64) {
        int h = i >> 6, o = i & 63;
        g_w2T[i]   = snn_w2[o * 1024 + h];
        g_nnw2T[i] = nn_w2[o * 1024 + h];
    }
    if (i < 1600 * 256) {
        int k = i >> 8, o = i & 255;
        g_fcT[i] = fc_w[o * 1600 + k];
    }
    if (i < 384 * 64) {
        int c = i >> 6, o = i & 63;
        g_combT[i] = comb_w[o * 384 + c];
    }
}

// ---------------- SNN: one block (1024 thr) per batch row --------------------
// Active-neuron compaction (drive c <= ~0.05 provably never spikes). Phase 1:
// chunk-per-warp LIF dynamics write 100-step spike masks. Phase 2: stage active
// w2 rows into SMEM in 128-row tiles (each row loaded from L2 ONCE), then
// warp-per-timestep gathers rows from SMEM with plain fp32 adds — no atomics,
// deterministic ascending-h order, ~3x less smem-unit work than atomic RMW.
__global__ __launch_bounds__(1024, 2) void snn_kernel(const float* __restrict__ x,
                                                      const float* __restrict__ w1,
                                                      const float* __restrict__ b1,
                                                      const float* __restrict__ b2,
                                                      int B) {
    __shared__ float          s_cur2[100 * 64];  // [t][o]  (b2 pre-added)
    __shared__ unsigned       s_masks[100 * 32]; // [t][chunk] spike bits (compact)
    __shared__ float          s_tile[128 * 64];  // staged active rows
    __shared__ unsigned short s_idx[1024];       // compact -> neuron index
    __shared__ float          s_cval[1024];      // compact -> drive c
    __shared__ unsigned       s_gm[32];
    __shared__ int            s_wbase[32];
    __shared__ int            s_nact;
    __shared__ float          s_feats[5];

    int b   = blockIdx.x;
    int tid = threadIdx.x;
    int wid = tid >> 5;
    int l   = tid & 31;

    if (tid < 5) s_feats[tid] = x[b * 105 + tid];
    __syncthreads();

    // ---- drive c per neuron + compaction (deterministic prefix) ----
    float f0 = s_feats[0], f1 = s_feats[1], f2 = s_feats[2],
          f3 = s_feats[3], f4 = s_feats[4];
    const float* wr = w1 + tid * 5;
    float c = b1[tid] + f0 * wr[0] + f1 * wr[1] + f2 * wr[2] + f3 * wr[3] + f4 * wr[4];
    bool act = c > 0.049995f;   // inclusion margin; excluded neurons provably silent
    unsigned gm = __ballot_sync(0xffffffffu, act);
    if (l == 0) s_gm[wid] = gm;
    __syncthreads();
    if (tid < 32) {
        int cnt = __popc(s_gm[tid]);
        int incl = cnt;
        #pragma unroll
        for (int d = 1; d < 32; d <<= 1) {
            int v = __shfl_up_sync(0xffffffffu, incl, d);
            if (tid >= d) incl += v;
        }
        s_wbase[tid] = incl - cnt;
        if (tid == 31) s_nact = incl;
    }
    __syncthreads();
    if (act) {
        int pos = s_wbase[wid] + __popc(gm & ((1u << l) - 1u));
        s_idx[pos]  = (unsigned short)tid;
        s_cval[pos] = c;
    }
    __syncthreads();

    int nact   = s_nact;
    int chunks = (nact + 31) >> 5;      // <= 32

    // ---- phase 1: LIF dynamics, one compact chunk per warp ----
    if (wid < chunks) {
        int i = wid * 32 + l;
        float cc = (i < nact) ? s_cval[i] : -1e30f;
        float mem = 0.f, sp = 0.f;
        #pragma unroll 4
        for (int t = 0; t < 100; t++) {
            mem = __fmaf_rn(0.95f, mem, cc) - sp;
            bool s = mem > 1.0f;
            unsigned m = __ballot_sync(0xffffffffu, s);
            if (l == 0) s_masks[t * 32 + wid] = m;
            sp = s ? 1.0f : 0.0f;
        }
    }
    __syncthreads();

    // ---- phase 2: tiled gather; warp = timestep, lane owns outputs (2l,2l+1) --
    float b20 = b2[2 * l], b21 = b2[2 * l + 1];
    float2 acc[4];
    #pragma unroll
    for (int q = 0; q < 4; q++) acc[q] = make_float2(b20, b21);

    int ntiles = (nact + 127) >> 7;
    for (int T = 0; T < ntiles; T++) {
        int base = T * 128;
        int cnt  = min(128, nact - base);

        // stage: 8 threads per row, 8 floats each (coalesced 2x float4)
        for (int w = tid; w < cnt * 8; w += 1024) {
            int il = w >> 3, c8 = (w & 7) * 8;
            int hh = s_idx[base + il];
            float4 v0 = *(const float4*)(g_w2T + hh * 64 + c8);
            float4 v1 = *(const float4*)(g_w2T + hh * 64 + c8 + 4);
            *(float4*)(s_tile + il * 64 + c8)     = v0;
            *(float4*)(s_tile + il * 64 + c8 + 4) = v1;
        }
        __syncthreads();

        int c0   = base >> 5;              // 4*T
        int cend = min(c0 + 4, chunks);
        #pragma unroll
        for (int q = 0; q < 4; q++) {
            int t = wid + q * 32;
            if (t < 100) {
                float2 a = acc[q];
                for (int ci = c0; ci < cend; ci++) {
                    unsigned m = s_masks[t * 32 + ci];
                    const float* rowb = s_tile + (ci - c0) * 32 * 64;
                    while (m) {
                        int j = __ffs(m) - 1; m &= m - 1;
                        float2 v = *(const float2*)(rowb + j * 64 + 2 * l);
                        a.x += v.x; a.y += v.y;
                    }
                }
                acc[q] = a;
            }
        }
        __syncthreads();   // before next tile overwrites s_tile
    }

    #pragma unroll
    for (int q = 0; q < 4; q++) {
        int t = wid + q * 32;
        if (t < 100) *(float2*)(s_cur2 + t * 64 + 2 * l) = acc[q];
    }
    __syncthreads();

    // ---- phase 3: layer-2 LIF scan + mean ----
    if (tid < 64) {
        float mem = 0.f, sp = 0.f, sum = 0.f;
        #pragma unroll 4
        for (int t = 0; t < 100; t++) {
            mem = __fmaf_rn(0.95f, mem, s_cur2[t * 64 + tid]) - sp;
            bool s = mem > 1.0f;
            sp = s ? 1.0f : 0.0f;
            sum += sp;
        }
        g_snn[b * 64 + tid] = sum * 0.01f;
    }
}

// ---------------- plain MLP: 8 rows per block --------------------------------
__global__ __launch_bounds__(256) void nn_kernel(const float* __restrict__ x,
                                                 const float* __restrict__ w1,
                                                 const float* __restrict__ b1,
                                                 const float* __restrict__ b2,
                                                 int B) {
    __shared__ float s_h[8 * 1024];   // [r][h]
    __shared__ float s_f[8][5];

    int b0  = blockIdx.x * 8;
    int tid = threadIdx.x;

    if (tid < 40) {
        int r = tid / 5, k = tid % 5;
        s_f[r][k] = x[(b0 + r) * 105 + k];
    }
    __syncthreads();

    for (int j = 0; j < 4; j++) {
        int h = tid + 256 * j;
        const float* wr = w1 + h * 5;
        float w0 = wr[0], w1v = wr[1], w2v = wr[2], w3 = wr[3], w4 = wr[4];
        float bb = b1[h];
        #pragma unroll
        for (int r = 0; r < 8; r++) {
            float v = bb + s_f[r][0] * w0 + s_f[r][1] * w1v + s_f[r][2] * w2v +
                      s_f[r][3] * w3 + s_f[r][4] * w4;
            s_h[r * 1024 + h] = v > 0.f ? v : 0.f;
        }
    }
    __syncthreads();

    int o  = tid & 63;
    int rg = tid >> 6;
    float a0 = 0.f, a1 = 0.f;
    const float* h0 = s_h + (rg * 2) * 1024;
    const float* h1 = s_h + (rg * 2 + 1) * 1024;
    #pragma unroll 8
    for (int h = 0; h < 1024; h++) {
        float w = g_nnw2T[h * 64 + o];
        a0 += w * h0[h];
        a1 += w * h1[h];
    }
    float bo = b2[o];
    g_nn[(b0 + rg * 2) * 64 + o]     = a0 + bo;
    g_nn[(b0 + rg * 2 + 1) * 64 + o] = a1 + bo;
}

// ---------------- CNN: 32 rows/block, 512 thr (k-split), f32x2 FC ------------
#define CNN_SMEM_BYTES ((32 * 1600 + 32 * 102) * 4)

__global__ __launch_bounds__(512, 1) void cnn_kernel(const float* __restrict__ x,
                                                     const float* __restrict__ cw,
                                                     const float* __restrict__ cb,
                                                     const float* __restrict__ fcb,
                                                     int B) {
    extern __shared__ float sm[];
    float* s_p    = sm;                // pooled, transposed: [k][r] (1600 x 32)
    float* s_wave = sm + 32 * 1600;    // [r][102] zero-padded

    __shared__ float s_cw[96];
    __shared__ float s_cb[32];

    int b0  = blockIdx.x * 32;
    int tid = threadIdx.x;

    if (tid < 96) s_cw[tid] = cw[tid];
    if (tid < 32) s_cb[tid] = cb[tid];
    for (int i = tid; i < 32 * 102; i += 512) {
        int r = i / 102, q = i % 102;
        float v = 0.f;
        if (q >= 1 && q <= 100) v = x[(b0 + r) * 105 + 4 + q];
        s_wave[i] = v;
    }
    __syncthreads();

    // conv(pad=1,k=3) + bias + relu + maxpool2, transposed store
    for (int i = tid; i < 32 * 1600; i += 512) {
        int r   = i & 31;
        int pos = i >> 5;              // ch*50 + j
        int ch  = pos / 50;
        int j   = pos - ch * 50;
        const float* wv = s_wave + r * 102 + 2 * j;
        float w0 = s_cw[ch * 3], w1 = s_cw[ch * 3 + 1], w2 = s_cw[ch * 3 + 2];
        float bb = s_cb[ch];
        float c0 = bb + wv[0] * w0 + wv[1] * w1 + wv[2] * w2;
        float c1 = bb + wv[1] * w0 + wv[2] * w1 + wv[3] * w2;
        float m = fmaxf(c0, c1);
        s_p[pos * 32 + r] = m > 0.f ? m : 0.f;
    }
    __syncthreads();

    // FC 1600 -> 256: thread = (output o, k-half); 16 f32x2 accumulators (32 rows)
    int o  = tid & 255;
    int kh = tid >> 8;
    unsigned long long a[16];
    #pragma unroll
    for (int q = 0; q < 16; q++) a[q] = 0ull;

    int kbeg = kh * 800;
    const float* fp = g_fcT + (size_t)kbeg * 256 + o;
    const ulonglong2* rp = (const ulonglong2*)s_p + kbeg * 8;   // 8 x 16B per k

    for (int kk = 0; kk < 800; kk += 4) {
        float w0 = fp[0], w1 = fp[256], w2 = fp[512], w3 = fp[768];
        fp += 1024;
        unsigned long long W[4];
        asm("mov.b64 %0, {%1, %1};" : "=l"(W[0]) : "r"(__float_as_uint(w0)));
        asm("mov.b64 %0, {%1, %1};" : "=l"(W[1]) : "r"(__float_as_uint(w1)));
        asm("mov.b64 %0, {%1, %1};" : "=l"(W[2]) : "r"(__float_as_uint(w2)));
        asm("mov.b64 %0, {%1, %1};" : "=l"(W[3]) : "r"(__float_as_uint(w3)));
        #pragma unroll
        for (int u = 0; u < 4; u++) {
            #pragma unroll
            for (int j = 0; j < 8; j++) {
                ulonglong2 v = rp[u * 8 + j];
                asm("fma.rn.f32x2 %0, %1, %2, %0;" : "+l"(a[2 * j])     : "l"(v.x), "l"(W[u]));
                asm("fma.rn.f32x2 %0, %1, %2, %0;" : "+l"(a[2 * j + 1]) : "l"(v.y), "l"(W[u]));
            }
        }
        rp += 32;
    }

    // combine halves through g_cnn; a[2j] = rows (4j,4j+1), a[2j+1] = (4j+2,4j+3)
    if (kh == 1) {
        #pragma unroll
        for (int q = 0; q < 16; q++) {
            int r = (q >> 1) * 4 + (q & 1) * 2;
            float lo = __uint_as_float((unsigned)(a[q] & 0xffffffffull));
            float hi = __uint_as_float((unsigned)(a[q] >> 32));
            g_cnn[(b0 + r) * 256 + o]     = lo;
            g_cnn[(b0 + r + 1) * 256 + o] = hi;
        }
    }
    __syncthreads();
    if (kh == 0) {
        float fb = fcb[o];
        #pragma unroll
        for (int q = 0; q < 16; q++) {
            int r = (q >> 1) * 4 + (q & 1) * 2;
            float lo = __uint_as_float((unsigned)(a[q] & 0xffffffffull));
            float hi = __uint_as_float((unsigned)(a[q] >> 32));
            int r0 = (b0 + r) * 256 + o;
            int r1 = (b0 + r + 1) * 256 + o;
            g_cnn[r0] = lo + fb + g_cnn[r0];
            g_cnn[r1] = hi + fb + g_cnn[r1];
        }
    }
}

// ---------------- combiner ----------------------------------------------------
__global__ __launch_bounds__(256) void comb_kernel(const float* __restrict__ cbias,
                                                   float* __restrict__ out,
                                                   int B) {
    __shared__ float s_c[16 * 384];   // [r][c]
    int b0  = blockIdx.x * 16;
    int tid = threadIdx.x;

    for (int i = tid; i < 16 * 64; i += 256) {
        int r = i >> 6, o = i & 63;
        s_c[r * 384 + o]      = g_snn[(b0 + r) * 64 + o];
        s_c[r * 384 + 64 + o] = g_nn[(b0 + r) * 64 + o];
    }
    for (int i = tid; i < 16 * 256; i += 256) {
        int r = i >> 8, o = i & 255;
        s_c[r * 384 + 128 + o] = g_cnn[(b0 + r) * 256 + o];
    }
    __syncthreads();

    int o  = tid & 63;
    int rg = tid >> 6;
    float a[4] = {0.f, 0.f, 0.f, 0.f};
    for (int c = 0; c < 384; c++) {
        float w = g_combT[c * 64 + o];
        const float* pr = s_c + (rg * 4) * 384 + c;
        a[0] += w * pr[0];
        a[1] += w * pr[384];
        a[2] += w * pr[2 * 384];
        a[3] += w * pr[3 * 384];
    }
    float bo = cbias[o];
    #pragma unroll
    for (int q = 0; q < 4; q++)
        out[(b0 + rg * 4 + q) * 64 + o] = a[q] + bo;
}

// ---------------- launch -------------------------------------------------------
extern "C" void kernel_launch(void* const* d_in, const int* in_sizes, int n_in,
                              void* d_out, int out_size) {
    const float* x      = (const float*)d_in[0];
    const float* snn_w1 = (const float*)d_in[1];
    const float* snn_b1 = (const float*)d_in[2];
    const float* snn_w2 = (const float*)d_in[3];
    const float* snn_b2 = (const float*)d_in[4];
    const float* nn_w1  = (const float*)d_in[5];
    const float* nn_b1  = (const float*)d_in[6];
    const float* nn_w2  = (const float*)d_in[7];
    const float* nn_b2  = (const float*)d_in[8];
    const float* conv_w = (const float*)d_in[9];
    const float* conv_b = (const float*)d_in[10];
    const float* fc_w   = (const float*)d_in[11];
    const float* fc_b   = (const float*)d_in[12];
    const float* comb_w = (const float*)d_in[13];
    const float* comb_b = (const float*)d_in[14];

    int B = in_sizes[0] / 105;

    // lazy one-time stream/event setup (first call is the uncaptured
    // correctness run; capture call reuses the handles — no allocations)
    static cudaStream_t s1 = nullptr, s2 = nullptr;
    static cudaEvent_t  e0 = nullptr, e1 = nullptr, e2 = nullptr;
    static bool attr_set = false;
    if (!s1) {
        cudaStreamCreateWithFlags(&s1, cudaStreamNonBlocking);
        cudaStreamCreateWithFlags(&s2, cudaStreamNonBlocking);
        cudaEventCreateWithFlags(&e0, cudaEventDisableTiming);
        cudaEventCreateWithFlags(&e1, cudaEventDisableTiming);
        cudaEventCreateWithFlags(&e2, cudaEventDisableTiming);
    }
    if (!attr_set) {
        cudaFuncSetAttribute(cnn_kernel, cudaFuncAttributeMaxDynamicSharedMemorySize,
                             CNN_SMEM_BYTES);
        attr_set = true;
    }

    // prep on capture stream; fork snn (s1) and nn (s2); cnn stays on capture
    // stream; comb joins all three branches.
    prep_kernel<<<1600, 256>>>(snn_w2, nn_w2, fc_w, comb_w);
    cudaEventRecord(e0, 0);

    cudaStreamWaitEvent(s1, e0, 0);
    snn_kernel<<<B, 1024, 0, s1>>>(x, snn_w1, snn_b1, snn_b2, B);
    cudaEventRecord(e1, s1);

    cudaStreamWaitEvent(s2, e0, 0);
    nn_kernel<<<B / 8, 256, 0, s2>>>(x, nn_w1, nn_b1, nn_b2, B);
    cudaEventRecord(e2, s2);

    cnn_kernel<<<B / 32, 512, CNN_SMEM_BYTES>>>(x, conv_w, conv_b, fc_b, B);

    cudaStreamWaitEvent(0, e1, 0);
    cudaStreamWaitEvent(0, e2, 0);
    comb_kernel<<<B / 16, 256>>>(comb_b, (float*)d_out, B);
}